// round 14
// baseline (speedup 1.0000x reference)
#include <cuda_runtime.h>
#include <cuda_fp16.h>
#include <cstdint>

// ---------------- problem constants ----------------
#define KCL      1024
#define DIM      128
#define BROWS    262144
#define M_CTA    256              // rows per CTA (pass 1)
#define NCHUNK_P 128              // protos per chunk
#define NCHUNKS  8                // 1024/128
#define BROW_B   272              // padded bytes per proto row -> LDSM conflict-free
#define HI_BLK   (NCHUNK_P * BROW_B)        // 34816 bytes per hi chunk
// hi-pass worst-case error: delta <= 9.9e-4*||e||; 2*delta = 1.97e-3
#define C2_CERT  2.3e-3f          // pass-1 v1-v2 certification
#define C4_CERT  2.3e-3f          // refineA v1-v4 top-3-candidate certification

// pass1 smem: buf[2] + rowBest[256] + mbar[2]
#define P1_MB    (2 * HI_BLK + 1024)
#define P1_SMEM  (P1_MB + 32)
// refineA smem: buf[2] + rowIdx[128] + cCand[128] + mbar[2]
#define RA_RI    (2 * HI_BLK)
#define RA_CC    (RA_RI + 512)
#define RA_MB    (RA_CC + 2048)
#define RA_SMEM  (RA_MB + 32)

typedef uint32_t u32;
typedef unsigned long long ull;

// ---------------- device scratch (no allocs) ----------------
__device__ __align__(16) char  g_Bimg[NCHUNKS * HI_BLK];  // hi fp16 proto image (padded)
__device__ __align__(16) float g_proto_n[KCL * DIM];      // fp32 normalized protos
__device__ __align__(16) float g_sums[KCL * DIM];
__device__ float g_counts[KCL];
__device__ int   g_flag[BROWS];    // rows uncertified by pass-1
__device__ int   g_listB[BROWS];   // rows needing full exact scan
__device__ int   g_nF, g_nB;

// ---------------- PTX helpers (plain-sm_100-legal) ----------
__device__ __forceinline__ u32 smem_u32(const void* p) {
    u32 a;
    asm("{ .reg .u64 t; cvta.to.shared.u64 t, %1; cvt.u32.u64 %0, t; }" : "=r"(a) : "l"(p));
    return a;
}
__device__ __forceinline__ void mbar_init(u32 a, u32 cnt) {
    asm volatile("mbarrier.init.shared.b64 [%0], %1;" :: "r"(a), "r"(cnt) : "memory");
}
__device__ __forceinline__ void mbar_expect_tx(u32 a, u32 bytes) {
    asm volatile("mbarrier.arrive.expect_tx.shared.b64 _, [%0], %1;"
                 :: "r"(a), "r"(bytes) : "memory");
}
__device__ __forceinline__ void mbar_wait(u32 a, u32 parity) {
    asm volatile(
        "{\n\t.reg .pred P;\n"
        "WL_%=:\n\t"
        "mbarrier.try_wait.parity.acquire.cta.shared::cta.b64 P, [%0], %1, 0x989680;\n\t"
        "@P bra WD_%=;\n\t"
        "bra WL_%=;\n"
        "WD_%=:\n\t}"
        :: "r"(a), "r"(parity) : "memory");
}
// bulk copy global -> shared, completion via mbarrier (SASS: UBLKCP.S.G)
__device__ __forceinline__ void bulk_g2s(u32 dst, const void* src, u32 bytes, u32 mbar) {
    asm volatile(
        "cp.async.bulk.shared::cluster.global.mbarrier::complete_tx::bytes "
        "[%0], [%1], %2, [%3];"
        :: "r"(dst), "l"(src), "r"(bytes), "r"(mbar) : "memory");
}
__device__ __forceinline__ void ldsm4(u32* r, u32 addr) {
    asm volatile("ldmatrix.sync.aligned.m8n8.x4.shared.b16 {%0,%1,%2,%3}, [%4];"
                 : "=r"(r[0]), "=r"(r[1]), "=r"(r[2]), "=r"(r[3]) : "r"(addr));
}
__device__ __forceinline__ void mma16(float* d, const u32* a, const u32* b) {
    asm volatile(
        "mma.sync.aligned.m16n8k16.row.col.f32.f16.f16.f32 "
        "{%0,%1,%2,%3}, {%4,%5,%6,%7}, {%8,%9}, {%0,%1,%2,%3};"
        : "+f"(d[0]), "+f"(d[1]), "+f"(d[2]), "+f"(d[3])
        : "r"(a[0]), "r"(a[1]), "r"(a[2]), "r"(a[3]), "r"(b[0]), "r"(b[1]));
}
__device__ __forceinline__ void red4(float* gp, float4 v) {
    asm volatile("red.global.add.v4.f32 [%0], {%1,%2,%3,%4};"
                 :: "l"(gp), "f"(v.x), "f"(v.y), "f"(v.z), "f"(v.w) : "memory");
}
__device__ __forceinline__ u32 hi2(float2 v) {
    __half2 h2 = __halves2half2(__float2half_rn(v.x), __float2half_rn(v.y));
    return *(u32*)&h2;
}
__device__ __forceinline__ void ffma2(ull &d, ull a, ull b) {
    asm("fma.rn.f32x2 %0, %1, %2, %0;" : "+l"(d) : "l"(a), "l"(b));
}
__device__ __forceinline__ float2 unpack2(ull v) {
    float2 f;
    asm("mov.b64 {%0, %1}, %2;" : "=f"(f.x), "=f"(f.y) : "l"(v));
    return f;
}
// top-4 insert (values) with top-3 indices (refineA only, ~6% of rows)
__device__ __forceinline__ void fold4(float x, int c,
    float& v1, int& i1, float& v2, int& i2, float& v3, int& i3, float& v4) {
    if (x > v1)      { v4 = v3; v3 = v2; i3 = i2; v2 = v1; i2 = i1; v1 = x; i1 = c; }
    else if (x > v2) { v4 = v3; v3 = v2; i3 = i2; v2 = x; i2 = c; }
    else if (x > v3) { v4 = v3; v3 = x; i3 = c; }
    else if (x > v4) { v4 = x; }
}

// ---------------------------------------------------------------------------
// Prep: normalize prototypes (x / max(||x||, eps)) -> g_proto_n (fp32) and
// hi-fp16 padded image. Zero sums/counts/list counters.
__global__ void prep_kernel(const float* __restrict__ proto) {
    int k = blockIdx.x, t = threadIdx.x;
    float v = proto[k * DIM + t];
    float s = v * v;
    #pragma unroll
    for (int m = 16; m; m >>= 1) s += __shfl_xor_sync(0xffffffffu, s, m);
    __shared__ float ws[4];
    if ((t & 31) == 0) ws[t >> 5] = s;
    __syncthreads();
    float pn = v * (1.0f / fmaxf(sqrtf(ws[0] + ws[1] + ws[2] + ws[3]), 1e-12f));

    g_proto_n[k * DIM + t] = pn;
    int chunk = k >> 7, n = k & 127;
    *(__half*)(g_Bimg + (size_t)chunk * HI_BLK + n * BROW_B + t * 2) = __float2half_rn(pn);

    g_sums[k * DIM + t] = 0.0f;
    if (t == 0) g_counts[k] = 0.0f;
    if (k == 0 && t == 0) { g_nF = 0; g_nB = 0; }
}

// ---------------------------------------------------------------------------
// Pass 1: hi-fp16 GEMM, bulk-copy staging, BRANCHLESS top-2 tracking.
// Certified rows scatter; uncertified -> g_flag.
__global__ void __launch_bounds__(256, 2)
pass1_kernel(const float* __restrict__ emb) {
    extern __shared__ char dsm[];
    const u32 sbase = smem_u32(dsm);
    int* rowBest = (int*)(dsm + 2 * HI_BLK);
    const u32 mb0 = sbase + P1_MB, mb1 = mb0 + 8;

    const int tid  = threadIdx.x;
    const int wid  = tid >> 5;
    const int lane = tid & 31;
    const int g    = lane >> 2;
    const int qi   = lane & 3;
    const int rowBase = blockIdx.x * M_CTA;
    const float* ebase = emb + (size_t)rowBase * DIM;

    if (tid == 0) { mbar_init(mb0, 1); mbar_init(mb1, 1); }
    __syncthreads();
    if (tid == 0) {
        mbar_expect_tx(mb0, HI_BLK); bulk_g2s(sbase, g_Bimg, HI_BLK, mb0);
        mbar_expect_tx(mb1, HI_BLK); bulk_g2s(sbase + HI_BLK, g_Bimg + HI_BLK, HI_BLK, mb1);
    }

    // ---- A hi fragments + row norms (overlaps with bulk latency) ----
    u32 AHI[2][8][4];
    float nrm2[4] = {0.f, 0.f, 0.f, 0.f};
    #pragma unroll
    for (int t2 = 0; t2 < 2; ++t2) {
        const int rA = t2 * 128 + wid * 16 + g;
        #pragma unroll
        for (int ks = 0; ks < 8; ++ks) {
            const int c0 = ks * 16 + 2 * qi;
            float2 v0 = *(const float2*)(ebase + (size_t)rA * DIM + c0);
            float2 v1 = *(const float2*)(ebase + (size_t)(rA + 8) * DIM + c0);
            float2 v2 = *(const float2*)(ebase + (size_t)rA * DIM + c0 + 8);
            float2 v3 = *(const float2*)(ebase + (size_t)(rA + 8) * DIM + c0 + 8);
            AHI[t2][ks][0] = hi2(v0); AHI[t2][ks][1] = hi2(v1);
            AHI[t2][ks][2] = hi2(v2); AHI[t2][ks][3] = hi2(v3);
            nrm2[t2 * 2]     += v0.x * v0.x + v0.y * v0.y + v2.x * v2.x + v2.y * v2.y;
            nrm2[t2 * 2 + 1] += v1.x * v1.x + v1.y * v1.y + v3.x * v3.x + v3.y * v3.y;
        }
    }
    #pragma unroll
    for (int m = 1; m <= 2; m <<= 1)
        #pragma unroll
        for (int q = 0; q < 4; ++q)
            nrm2[q] += __shfl_xor_sync(0xffffffffu, nrm2[q], m);

    const u32 laneOff = (u32)((lane & 7) * BROW_B + (lane >> 3) * 16);

    float v1a[4], v2a[4]; int i1a[4];
    #pragma unroll
    for (int q = 0; q < 4; ++q) { v1a[q] = -3.4e38f; v2a[q] = -3.4e38f; i1a[q] = 0; }

    for (int c = 0; c < NCHUNKS; ++c) {
        const int s = c & 1;
        mbar_wait(s ? mb1 : mb0, (u32)((c >> 1) & 1));
        const u32 bb = sbase + (u32)s * HI_BLK;

        #pragma unroll 1
        for (int nt = 0; nt < 16; ++nt) {
            float d0[4] = {0.f, 0.f, 0.f, 0.f};
            float d1[4] = {0.f, 0.f, 0.f, 0.f};
            u32 B[8];
            const u32 ntOff = bb + (u32)nt * (8 * BROW_B) + laneOff;
            ldsm4(B, ntOff); ldsm4(B + 4, ntOff + 64);
            #pragma unroll
            for (int ks = 0; ks < 4; ++ks) {
                mma16(d0, AHI[0][ks], &B[2 * ks]);
                mma16(d1, AHI[1][ks], &B[2 * ks]);
            }
            ldsm4(B, ntOff + 128); ldsm4(B + 4, ntOff + 192);
            #pragma unroll
            for (int ks = 4; ks < 8; ++ks) {
                mma16(d0, AHI[0][ks], &B[2 * (ks - 4)]);
                mma16(d1, AHI[1][ks], &B[2 * (ks - 4)]);
            }
            const int c0 = c * NCHUNK_P + nt * 8 + 2 * qi;
            // branchless top-2 fold: exact top-2 of {v1,v2,da,db};
            // ties produce v2==v1 (forces flag) and first-max index wins.
            #pragma unroll
            for (int q = 0; q < 4; ++q) {
                const float da = (q < 2) ? d0[q * 2] : d1[(q - 2) * 2];
                const float db = (q < 2) ? d0[q * 2 + 1] : d1[(q - 2) * 2 + 1];
                const float m  = fmaxf(da, db);
                const float sm = fminf(da, db);
                const int   ci = c0 + ((db > da) ? 1 : 0);
                v2a[q] = fmaxf(fmaxf(v2a[q], sm), fminf(v1a[q], m));
                i1a[q] = (m > v1a[q]) ? ci : i1a[q];
                v1a[q] = fmaxf(v1a[q], m);
            }
        }
        __syncthreads();
        if (c + 2 < NCHUNKS && tid == 0) {
            const u32 mb = s ? mb1 : mb0;
            mbar_expect_tx(mb, HI_BLK);
            bulk_g2s(sbase + (u32)s * HI_BLK, g_Bimg + (size_t)(c + 2) * HI_BLK, HI_BLK, mb);
        }
    }

    // quad reduce top-2 (lanes of a quad hold disjoint cluster columns)
    #pragma unroll
    for (int m = 1; m <= 2; m <<= 1) {
        #pragma unroll
        for (int q = 0; q < 4; ++q) {
            float ov1 = __shfl_xor_sync(0xffffffffu, v1a[q], m);
            int   oi1 = __shfl_xor_sync(0xffffffffu, i1a[q], m);
            float ov2 = __shfl_xor_sync(0xffffffffu, v2a[q], m);
            if (ov1 > v1a[q]) {
                v2a[q] = fmaxf(v1a[q], ov2); v1a[q] = ov1; i1a[q] = oi1;
            } else if (ov1 == v1a[q]) {
                v2a[q] = v1a[q];                     // exact tie -> force flag
                i1a[q] = min(i1a[q], oi1);
            } else {
                v2a[q] = fmaxf(v2a[q], ov1);
            }
        }
    }

    if (qi == 0) {
        #pragma unroll
        for (int q = 0; q < 4; ++q) {
            const int rl = (q >> 1) * 128 + wid * 16 + (q & 1) * 8 + g;
            if (v1a[q] - v2a[q] > C2_CERT * sqrtf(nrm2[q])) {
                rowBest[rl] = i1a[q];
            } else {
                rowBest[rl] = -1;
                int pos = atomicAdd(&g_nF, 1);
                g_flag[pos] = rowBase + rl;
            }
        }
    }
    __syncthreads();

    // ---- scatter certified rows ----
    {
        int rb = rowBest[tid];
        if (rb >= 0) atomicAdd(&g_counts[rb], 1.0f);
    }
    const float4* e4 = (const float4*)ebase;
    #pragma unroll 4
    for (int it = 0; it < 32; ++it) {
        int idx = it * 256 + tid;
        int r  = idx >> 5;
        int c4 = idx & 31;
        int rb = rowBest[r];
        if (rb >= 0) red4(&g_sums[rb * DIM + c4 * 4], e4[r * 32 + c4]);
    }
}

// ---------------------------------------------------------------------------
// RefineA: hi-fp16 GEMM on gathered 128-row flagged tiles (bulk staging) with
// top-4 tracking, then INLINE exact fp32 resolution of the top-3 candidates
// + scatter. Rows failing the top-3 cert go to g_listB.
__global__ void __launch_bounds__(256, 2)
refineA_kernel(const float* __restrict__ emb) {
    extern __shared__ char dsm[];
    const u32 sbase = smem_u32(dsm);
    int*  rowIdx = (int*)(dsm + RA_RI);
    int4* cCand  = (int4*)(dsm + RA_CC);
    const u32 mb0 = sbase + RA_MB, mb1 = mb0 + 8;

    const int tid  = threadIdx.x;
    const int wid  = tid >> 5;
    const int lane = tid & 31;
    const int g    = lane >> 2;
    const int qi   = lane & 3;

    const int nf = *(volatile int*)&g_nF;
    const int nTiles = (nf + 127) >> 7;
    const u32 laneOff = (u32)((lane & 7) * BROW_B + (lane >> 3) * 16);
    const float4* p4 = (const float4*)g_proto_n;

    if (tid == 0) { mbar_init(mb0, 1); mbar_init(mb1, 1); }
    __syncthreads();

    int pc0 = 0, pc1 = 0;   // per-stage completed-phase counters (cross-tile)

    for (int t = blockIdx.x; t < nTiles; t += gridDim.x) {
        if (tid < 128) {
            int srci = t * 128 + tid;
            rowIdx[tid] = (srci < nf) ? g_flag[srci] : -1;
        }
        __syncthreads();
        if (tid == 0) {
            mbar_expect_tx(mb0, HI_BLK); bulk_g2s(sbase, g_Bimg, HI_BLK, mb0);
            mbar_expect_tx(mb1, HI_BLK); bulk_g2s(sbase + HI_BLK, g_Bimg + HI_BLK, HI_BLK, mb1);
        }

        const int r0 = rowIdx[wid * 16 + g];
        const int r1 = rowIdx[wid * 16 + g + 8];
        const float* e0 = emb + (size_t)max(r0, 0) * DIM;
        const float* e1 = emb + (size_t)max(r1, 0) * DIM;

        u32 AHI[8][4];
        float nrm2[2] = {0.f, 0.f};
        #pragma unroll
        for (int ks = 0; ks < 8; ++ks) {
            const int c0 = ks * 16 + 2 * qi;
            float2 v0 = *(const float2*)(e0 + c0);
            float2 v1 = *(const float2*)(e1 + c0);
            float2 v2 = *(const float2*)(e0 + c0 + 8);
            float2 v3 = *(const float2*)(e1 + c0 + 8);
            AHI[ks][0] = hi2(v0); AHI[ks][1] = hi2(v1);
            AHI[ks][2] = hi2(v2); AHI[ks][3] = hi2(v3);
            nrm2[0] += v0.x * v0.x + v0.y * v0.y + v2.x * v2.x + v2.y * v2.y;
            nrm2[1] += v1.x * v1.x + v1.y * v1.y + v3.x * v3.x + v3.y * v3.y;
        }
        #pragma unroll
        for (int m = 1; m <= 2; m <<= 1) {
            nrm2[0] += __shfl_xor_sync(0xffffffffu, nrm2[0], m);
            nrm2[1] += __shfl_xor_sync(0xffffffffu, nrm2[1], m);
        }

        float V1[2], V2[2], V3[2], V4[2];
        int   I1[2], I2[2], I3[2];
        #pragma unroll
        for (int q = 0; q < 2; ++q) {
            V1[q] = V2[q] = V3[q] = V4[q] = -3.4e38f;
            I1[q] = I2[q] = I3[q] = 0;
        }

        for (int c = 0; c < NCHUNKS; ++c) {
            const int s = c & 1;
            mbar_wait(s ? mb1 : mb0, (u32)((s ? pc1 : pc0) & 1));
            const u32 bb = sbase + (u32)s * HI_BLK;

            #pragma unroll 1
            for (int nt = 0; nt < 16; ++nt) {
                float d[4] = {0.f, 0.f, 0.f, 0.f};
                u32 B[8];
                const u32 ntOff = bb + (u32)nt * (8 * BROW_B) + laneOff;
                ldsm4(B, ntOff); ldsm4(B + 4, ntOff + 64);
                #pragma unroll
                for (int ks = 0; ks < 4; ++ks) mma16(d, AHI[ks], &B[2 * ks]);
                ldsm4(B, ntOff + 128); ldsm4(B + 4, ntOff + 192);
                #pragma unroll
                for (int ks = 4; ks < 8; ++ks) mma16(d, AHI[ks], &B[2 * (ks - 4)]);

                const int c0 = c * NCHUNK_P + nt * 8 + 2 * qi;
                fold4(d[0], c0,     V1[0], I1[0], V2[0], I2[0], V3[0], I3[0], V4[0]);
                fold4(d[1], c0 + 1, V1[0], I1[0], V2[0], I2[0], V3[0], I3[0], V4[0]);
                fold4(d[2], c0,     V1[1], I1[1], V2[1], I2[1], V3[1], I3[1], V4[1]);
                fold4(d[3], c0 + 1, V1[1], I1[1], V2[1], I2[1], V3[1], I3[1], V4[1]);
            }
            if (s) ++pc1; else ++pc0;
            __syncthreads();
            if (c + 2 < NCHUNKS && tid == 0) {
                const u32 mb = s ? mb1 : mb0;
                mbar_expect_tx(mb, HI_BLK);
                bulk_g2s(sbase + (u32)s * HI_BLK, g_Bimg + (size_t)(c + 2) * HI_BLK, HI_BLK, mb);
            }
        }

        // quad merge of top-4 lists
        #pragma unroll
        for (int m = 1; m <= 2; m <<= 1) {
            #pragma unroll
            for (int q = 0; q < 2; ++q) {
                float ov1 = __shfl_xor_sync(0xffffffffu, V1[q], m);
                int   oi1 = __shfl_xor_sync(0xffffffffu, I1[q], m);
                float ov2 = __shfl_xor_sync(0xffffffffu, V2[q], m);
                int   oi2 = __shfl_xor_sync(0xffffffffu, I2[q], m);
                float ov3 = __shfl_xor_sync(0xffffffffu, V3[q], m);
                int   oi3 = __shfl_xor_sync(0xffffffffu, I3[q], m);
                float ov4 = __shfl_xor_sync(0xffffffffu, V4[q], m);
                fold4(ov1, oi1, V1[q], I1[q], V2[q], I2[q], V3[q], I3[q], V4[q]);
                fold4(ov2, oi2, V1[q], I1[q], V2[q], I2[q], V3[q], I3[q], V4[q]);
                fold4(ov3, oi3, V1[q], I1[q], V2[q], I2[q], V3[q], I3[q], V4[q]);
                V4[q] = fmaxf(V4[q], ov4);
            }
        }

        if (qi == 0) {
            #pragma unroll
            for (int q = 0; q < 2; ++q) {
                const int rl = wid * 16 + q * 8 + g;
                const int ok = (V1[q] - V4[q] > C4_CERT * sqrtf(nrm2[q])) ? 1 : 0;
                cCand[rl] = make_int4(I1[q], I2[q], I3[q], ok);
            }
        }
        __syncthreads();

        // ---- inline exact resolution: warp w handles tile rows [w*16, w*16+16) ----
        for (int rr = wid * 16; rr < wid * 16 + 16; ++rr) {
            const int row = rowIdx[rr];
            if (row < 0) continue;
            const int4 cd = cCand[rr];
            if (!cd.w) {
                if (lane == 0) { int pos = atomicAdd(&g_nB, 1); g_listB[pos] = row; }
                continue;
            }
            const float4 ef = ((const float4*)(emb + (size_t)row * DIM))[lane];
            float4 pa = p4[cd.x * 32 + lane];
            float4 pb = p4[cd.y * 32 + lane];
            float4 pc = p4[cd.z * 32 + lane];
            float d1 = fmaf(ef.x, pa.x, fmaf(ef.y, pa.y, fmaf(ef.z, pa.z, ef.w * pa.w)));
            float d2 = fmaf(ef.x, pb.x, fmaf(ef.y, pb.y, fmaf(ef.z, pb.z, ef.w * pb.w)));
            float d3 = fmaf(ef.x, pc.x, fmaf(ef.y, pc.y, fmaf(ef.z, pc.z, ef.w * pc.w)));
            #pragma unroll
            for (int m = 16; m; m >>= 1) {
                d1 += __shfl_xor_sync(0xffffffffu, d1, m);
                d2 += __shfl_xor_sync(0xffffffffu, d2, m);
                d3 += __shfl_xor_sync(0xffffffffu, d3, m);
            }
            float bv = d1; int bi = cd.x;
            if (d2 > bv || (d2 == bv && cd.y < bi)) { bv = d2; bi = cd.y; }
            if (d3 > bv || (d3 == bv && cd.z < bi)) { bv = d3; bi = cd.z; }
            if (lane == 0) atomicAdd(&g_counts[bi], 1.0f);
            red4(&g_sums[bi * DIM + lane * 4], ef);
        }
        __syncthreads();   // rowIdx/cCand reuse next tile
    }
}

// ---------------------------------------------------------------------------
// RefineB: tiled exact fp32 GEMM over listB rows. 32 rows/tile in smem,
// 512 threads (16 per row), f32x2 packed FMA, no inner shuffles.
__global__ void __launch_bounds__(512, 1)
refineB_kernel(const float* __restrict__ emb) {
    __shared__ float erow[32][132];
    __shared__ int   rid[32];
    __shared__ float rv[512];
    __shared__ int   ri[512];

    const int tid = threadIdx.x;
    const int nB = *(volatile int*)&g_nB;
    const int nTiles = (nB + 31) >> 5;

    const int r   = tid >> 4;       // row 0..31
    const int t16 = tid & 15;       // 0..15

    for (int t = blockIdx.x; t < nTiles; t += gridDim.x) {
        if (tid < 32) rid[tid] = (t * 32 + tid < nB) ? g_listB[t * 32 + tid] : -1;
        __syncthreads();
        // load 32 emb rows into smem (1024 float4s / 512 threads = 2 each)
        #pragma unroll
        for (int u = 0; u < 2; ++u) {
            int idx = u * 512 + tid;
            int rr = idx >> 5, c4 = idx & 31;
            int row = rid[rr];
            float4 v = make_float4(0.f, 0.f, 0.f, 0.f);
            if (row >= 0) v = ((const float4*)(emb + (size_t)row * DIM))[c4];
            erow[rr][c4 * 4 + 0] = v.x; erow[rr][c4 * 4 + 1] = v.y;
            erow[rr][c4 * 4 + 2] = v.z; erow[rr][c4 * 4 + 3] = v.w;
        }
        __syncthreads();

        // thread covers clusters c = t16 + 16*j, j < 64 (ascending => first-max)
        const ull* e2 = (const ull*)erow[r];
        float bv = -3.4e38f; int bi = 0;
        for (int j = 0; j < 64; ++j) {
            const int c = t16 + 16 * j;
            const ulonglong2* pu = (const ulonglong2*)(g_proto_n + c * DIM);
            ull a0 = 0ull, a1 = 0ull;
            #pragma unroll
            for (int d = 0; d < 32; ++d) {
                ulonglong2 P = pu[d];
                ffma2(a0, e2[2 * d],     P.x);
                ffma2(a1, e2[2 * d + 1], P.y);
            }
            float2 f0 = unpack2(a0), f1 = unpack2(a1);
            float dsum = (f0.x + f0.y) + (f1.x + f1.y);
            if (dsum > bv) { bv = dsum; bi = c; }
        }
        rv[tid] = bv; ri[tid] = bi;
        __syncthreads();

        // row-leader merges 16 partials (value desc, index asc tie-break)
        if (t16 == 0 && rid[r] >= 0) {
            float mv = rv[tid]; int mi = ri[tid];
            #pragma unroll
            for (int u = 1; u < 16; ++u) {
                float ov = rv[tid + u]; int oi = ri[tid + u];
                if (ov > mv || (ov == mv && oi < mi)) { mv = ov; mi = oi; }
            }
            ri[tid] = mi;                 // publish winner at slot r*16
            atomicAdd(&g_counts[mi], 1.0f);
        }
        __syncthreads();

        // scatter: 32 rows x 32 float4 = 1024 slots / 512 threads = 2 each
        #pragma unroll
        for (int u = 0; u < 2; ++u) {
            int idx = u * 512 + tid;
            int rr = idx >> 5, c4 = idx & 31;
            if (rid[rr] >= 0) {
                int bidx = ri[rr * 16];
                float4 v = make_float4(erow[rr][c4 * 4 + 0], erow[rr][c4 * 4 + 1],
                                       erow[rr][c4 * 4 + 2], erow[rr][c4 * 4 + 3]);
                red4(&g_sums[bidx * DIM + c4 * 4], v);
            }
        }
        __syncthreads();
    }
}

// ---------------------------------------------------------------------------
__global__ void finalize_kernel(const float* __restrict__ proto,
                                float* __restrict__ out) {
    int i = blockIdx.x * blockDim.x + threadIdx.x;
    int k = i >> 7;
    float c = g_counts[k];
    float p = proto[i];
    float m = g_sums[i] / fmaxf(c, 1.0f);
    out[i] = (c > 0.0f) ? (0.9f * p + 0.1f * m) : p;
}

// ---------------------------------------------------------------------------
extern "C" void kernel_launch(void* const* d_in, const int* in_sizes, int n_in,
                              void* d_out, int out_size) {
    const float* emb   = (const float*)d_in[0];
    const float* proto = (const float*)d_in[1];
    float* out = (float*)d_out;

    cudaFuncSetAttribute(pass1_kernel,
                         cudaFuncAttributeMaxDynamicSharedMemorySize, P1_SMEM);
    cudaFuncSetAttribute(refineA_kernel,
                         cudaFuncAttributeMaxDynamicSharedMemorySize, RA_SMEM);

    prep_kernel<<<KCL, DIM>>>(proto);
    pass1_kernel<<<BROWS / M_CTA, 256, P1_SMEM>>>(emb);
    refineA_kernel<<<148, 256, RA_SMEM>>>(emb);
    refineB_kernel<<<148, 512>>>(emb);
    finalize_kernel<<<(KCL * DIM) / 256, 256>>>(proto, out);
}

// round 15
// speedup vs baseline: 2.1176x; 2.1176x over previous
#include <cuda_runtime.h>
#include <cuda_fp16.h>
#include <cstdint>

// ---------------- problem constants ----------------
#define KCL      1024
#define DIM      128
#define BROWS    262144
#define M_CTA    256              // rows per CTA (pass 1)
#define NCHUNK_P 128              // protos per chunk
#define NCHUNKS  8                // 1024/128
#define BROW_B   272              // padded bytes per proto row -> LDSM conflict-free
#define HI_BLK   (NCHUNK_P * BROW_B)        // 34816 bytes per hi chunk
// hi-pass worst-case error: delta <= 9.9e-4*||e||; 2*delta = 1.97e-3
#define C2_CERT  2.3e-3f          // pass-1 v1-v2 certification
#define C4_CERT  2.3e-3f          // refineA v1-v4 top-3-candidate certification

// pass1 smem: buf[2] + rowBest[256] + mbar[2]
#define P1_MB    (2 * HI_BLK + 1024)
#define P1_SMEM  (P1_MB + 32)
// refineA smem: buf[2] + rowIdx[128] + cCand[128] + mbar[2]
#define RA_RI    (2 * HI_BLK)
#define RA_CC    (RA_RI + 512)
#define RA_MB    (RA_CC + 2048)
#define RA_SMEM  (RA_MB + 32)
// refineB smem: protoS[128][256] + eS[128][16] + rid[16] + win[16]
#define RB_ES    (128 * 256 * 4)            // 131072
#define RB_RID   (RB_ES + 128 * 16 * 4)     // 139264
#define RB_WIN   (RB_RID + 64)
#define RB_SMEM  (RB_WIN + 64 + 64)

typedef uint32_t u32;
typedef unsigned long long ull;

// ---------------- device scratch (no allocs) ----------------
__device__ __align__(16) char  g_Bimg[NCHUNKS * HI_BLK];  // hi fp16 proto image (padded)
__device__ __align__(16) float g_proto_n[KCL * DIM];      // fp32 normalized protos
__device__ __align__(16) float g_sums[KCL * DIM];
__device__ float g_counts[KCL];
__device__ int   g_flag[BROWS];    // rows uncertified by pass-1
__device__ int   g_listB[BROWS];   // rows needing full exact scan
__device__ int   g_nF, g_nB;

// ---------------- PTX helpers (plain-sm_100-legal) ----------
__device__ __forceinline__ u32 smem_u32(const void* p) {
    u32 a;
    asm("{ .reg .u64 t; cvta.to.shared.u64 t, %1; cvt.u32.u64 %0, t; }" : "=r"(a) : "l"(p));
    return a;
}
__device__ __forceinline__ void mbar_init(u32 a, u32 cnt) {
    asm volatile("mbarrier.init.shared.b64 [%0], %1;" :: "r"(a), "r"(cnt) : "memory");
}
__device__ __forceinline__ void mbar_expect_tx(u32 a, u32 bytes) {
    asm volatile("mbarrier.arrive.expect_tx.shared.b64 _, [%0], %1;"
                 :: "r"(a), "r"(bytes) : "memory");
}
__device__ __forceinline__ void mbar_wait(u32 a, u32 parity) {
    asm volatile(
        "{\n\t.reg .pred P;\n"
        "WL_%=:\n\t"
        "mbarrier.try_wait.parity.acquire.cta.shared::cta.b64 P, [%0], %1, 0x989680;\n\t"
        "@P bra WD_%=;\n\t"
        "bra WL_%=;\n"
        "WD_%=:\n\t}"
        :: "r"(a), "r"(parity) : "memory");
}
// bulk copy global -> shared, completion via mbarrier (SASS: UBLKCP.S.G)
__device__ __forceinline__ void bulk_g2s(u32 dst, const void* src, u32 bytes, u32 mbar) {
    asm volatile(
        "cp.async.bulk.shared::cluster.global.mbarrier::complete_tx::bytes "
        "[%0], [%1], %2, [%3];"
        :: "r"(dst), "l"(src), "r"(bytes), "r"(mbar) : "memory");
}
__device__ __forceinline__ void ldsm4(u32* r, u32 addr) {
    asm volatile("ldmatrix.sync.aligned.m8n8.x4.shared.b16 {%0,%1,%2,%3}, [%4];"
                 : "=r"(r[0]), "=r"(r[1]), "=r"(r[2]), "=r"(r[3]) : "r"(addr));
}
__device__ __forceinline__ void mma16(float* d, const u32* a, const u32* b) {
    asm volatile(
        "mma.sync.aligned.m16n8k16.row.col.f32.f16.f16.f32 "
        "{%0,%1,%2,%3}, {%4,%5,%6,%7}, {%8,%9}, {%0,%1,%2,%3};"
        : "+f"(d[0]), "+f"(d[1]), "+f"(d[2]), "+f"(d[3])
        : "r"(a[0]), "r"(a[1]), "r"(a[2]), "r"(a[3]), "r"(b[0]), "r"(b[1]));
}
__device__ __forceinline__ void red4(float* gp, float4 v) {
    asm volatile("red.global.add.v4.f32 [%0], {%1,%2,%3,%4};"
                 :: "l"(gp), "f"(v.x), "f"(v.y), "f"(v.z), "f"(v.w) : "memory");
}
__device__ __forceinline__ u32 hi2(float2 v) {
    __half2 h2 = __halves2half2(__float2half_rn(v.x), __float2half_rn(v.y));
    return *(u32*)&h2;
}
// top-4 insert (values) with top-3 indices (refineA only, ~6% of rows)
__device__ __forceinline__ void fold4(float x, int c,
    float& v1, int& i1, float& v2, int& i2, float& v3, int& i3, float& v4) {
    if (x > v1)      { v4 = v3; v3 = v2; i3 = i2; v2 = v1; i2 = i1; v1 = x; i1 = c; }
    else if (x > v2) { v4 = v3; v3 = v2; i3 = i2; v2 = x; i2 = c; }
    else if (x > v3) { v4 = v3; v3 = x; i3 = c; }
    else if (x > v4) { v4 = x; }
}

// ---------------------------------------------------------------------------
// Prep: normalize prototypes (x / max(||x||, eps)) -> g_proto_n (fp32) and
// hi-fp16 padded image. Zero sums/counts/list counters.
__global__ void prep_kernel(const float* __restrict__ proto) {
    int k = blockIdx.x, t = threadIdx.x;
    float v = proto[k * DIM + t];
    float s = v * v;
    #pragma unroll
    for (int m = 16; m; m >>= 1) s += __shfl_xor_sync(0xffffffffu, s, m);
    __shared__ float ws[4];
    if ((t & 31) == 0) ws[t >> 5] = s;
    __syncthreads();
    float pn = v * (1.0f / fmaxf(sqrtf(ws[0] + ws[1] + ws[2] + ws[3]), 1e-12f));

    g_proto_n[k * DIM + t] = pn;
    int chunk = k >> 7, n = k & 127;
    *(__half*)(g_Bimg + (size_t)chunk * HI_BLK + n * BROW_B + t * 2) = __float2half_rn(pn);

    g_sums[k * DIM + t] = 0.0f;
    if (t == 0) g_counts[k] = 0.0f;
    if (k == 0 && t == 0) { g_nF = 0; g_nB = 0; }
}

// ---------------------------------------------------------------------------
// Pass 1: hi-fp16 GEMM, bulk-copy staging, branchless top-2 tracking.
// Certified rows scatter; uncertified -> g_flag.
__global__ void __launch_bounds__(256, 2)
pass1_kernel(const float* __restrict__ emb) {
    extern __shared__ char dsm[];
    const u32 sbase = smem_u32(dsm);
    int* rowBest = (int*)(dsm + 2 * HI_BLK);
    const u32 mb0 = sbase + P1_MB, mb1 = mb0 + 8;

    const int tid  = threadIdx.x;
    const int wid  = tid >> 5;
    const int lane = tid & 31;
    const int g    = lane >> 2;
    const int qi   = lane & 3;
    const int rowBase = blockIdx.x * M_CTA;
    const float* ebase = emb + (size_t)rowBase * DIM;

    if (tid == 0) { mbar_init(mb0, 1); mbar_init(mb1, 1); }
    __syncthreads();
    if (tid == 0) {
        mbar_expect_tx(mb0, HI_BLK); bulk_g2s(sbase, g_Bimg, HI_BLK, mb0);
        mbar_expect_tx(mb1, HI_BLK); bulk_g2s(sbase + HI_BLK, g_Bimg + HI_BLK, HI_BLK, mb1);
    }

    // ---- A hi fragments + row norms (overlaps with bulk latency) ----
    u32 AHI[2][8][4];
    float nrm2[4] = {0.f, 0.f, 0.f, 0.f};
    #pragma unroll
    for (int t2 = 0; t2 < 2; ++t2) {
        const int rA = t2 * 128 + wid * 16 + g;
        #pragma unroll
        for (int ks = 0; ks < 8; ++ks) {
            const int c0 = ks * 16 + 2 * qi;
            float2 v0 = *(const float2*)(ebase + (size_t)rA * DIM + c0);
            float2 v1 = *(const float2*)(ebase + (size_t)(rA + 8) * DIM + c0);
            float2 v2 = *(const float2*)(ebase + (size_t)rA * DIM + c0 + 8);
            float2 v3 = *(const float2*)(ebase + (size_t)(rA + 8) * DIM + c0 + 8);
            AHI[t2][ks][0] = hi2(v0); AHI[t2][ks][1] = hi2(v1);
            AHI[t2][ks][2] = hi2(v2); AHI[t2][ks][3] = hi2(v3);
            nrm2[t2 * 2]     += v0.x * v0.x + v0.y * v0.y + v2.x * v2.x + v2.y * v2.y;
            nrm2[t2 * 2 + 1] += v1.x * v1.x + v1.y * v1.y + v3.x * v3.x + v3.y * v3.y;
        }
    }
    #pragma unroll
    for (int m = 1; m <= 2; m <<= 1)
        #pragma unroll
        for (int q = 0; q < 4; ++q)
            nrm2[q] += __shfl_xor_sync(0xffffffffu, nrm2[q], m);

    const u32 laneOff = (u32)((lane & 7) * BROW_B + (lane >> 3) * 16);

    float v1a[4], v2a[4]; int i1a[4];
    #pragma unroll
    for (int q = 0; q < 4; ++q) { v1a[q] = -3.4e38f; v2a[q] = -3.4e38f; i1a[q] = 0; }

    for (int c = 0; c < NCHUNKS; ++c) {
        const int s = c & 1;
        mbar_wait(s ? mb1 : mb0, (u32)((c >> 1) & 1));
        const u32 bb = sbase + (u32)s * HI_BLK;

        #pragma unroll 1
        for (int nt = 0; nt < 16; ++nt) {
            float d0[4] = {0.f, 0.f, 0.f, 0.f};
            float d1[4] = {0.f, 0.f, 0.f, 0.f};
            u32 B[8];
            const u32 ntOff = bb + (u32)nt * (8 * BROW_B) + laneOff;
            ldsm4(B, ntOff); ldsm4(B + 4, ntOff + 64);
            #pragma unroll
            for (int ks = 0; ks < 4; ++ks) {
                mma16(d0, AHI[0][ks], &B[2 * ks]);
                mma16(d1, AHI[1][ks], &B[2 * ks]);
            }
            ldsm4(B, ntOff + 128); ldsm4(B + 4, ntOff + 192);
            #pragma unroll
            for (int ks = 4; ks < 8; ++ks) {
                mma16(d0, AHI[0][ks], &B[2 * (ks - 4)]);
                mma16(d1, AHI[1][ks], &B[2 * (ks - 4)]);
            }
            const int c0 = c * NCHUNK_P + nt * 8 + 2 * qi;
            // branchless top-2 fold (exact; ties force flag; first-max index)
            #pragma unroll
            for (int q = 0; q < 4; ++q) {
                const float da = (q < 2) ? d0[q * 2] : d1[(q - 2) * 2];
                const float db = (q < 2) ? d0[q * 2 + 1] : d1[(q - 2) * 2 + 1];
                const float m  = fmaxf(da, db);
                const float sm = fminf(da, db);
                const int   ci = c0 + ((db > da) ? 1 : 0);
                v2a[q] = fmaxf(fmaxf(v2a[q], sm), fminf(v1a[q], m));
                i1a[q] = (m > v1a[q]) ? ci : i1a[q];
                v1a[q] = fmaxf(v1a[q], m);
            }
        }
        __syncthreads();
        if (c + 2 < NCHUNKS && tid == 0) {
            const u32 mb = s ? mb1 : mb0;
            mbar_expect_tx(mb, HI_BLK);
            bulk_g2s(sbase + (u32)s * HI_BLK, g_Bimg + (size_t)(c + 2) * HI_BLK, HI_BLK, mb);
        }
    }

    // quad reduce top-2 (lanes of a quad hold disjoint cluster columns)
    #pragma unroll
    for (int m = 1; m <= 2; m <<= 1) {
        #pragma unroll
        for (int q = 0; q < 4; ++q) {
            float ov1 = __shfl_xor_sync(0xffffffffu, v1a[q], m);
            int   oi1 = __shfl_xor_sync(0xffffffffu, i1a[q], m);
            float ov2 = __shfl_xor_sync(0xffffffffu, v2a[q], m);
            if (ov1 > v1a[q]) {
                v2a[q] = fmaxf(v1a[q], ov2); v1a[q] = ov1; i1a[q] = oi1;
            } else if (ov1 == v1a[q]) {
                v2a[q] = v1a[q];                     // exact tie -> force flag
                i1a[q] = min(i1a[q], oi1);
            } else {
                v2a[q] = fmaxf(v2a[q], ov1);
            }
        }
    }

    if (qi == 0) {
        #pragma unroll
        for (int q = 0; q < 4; ++q) {
            const int rl = (q >> 1) * 128 + wid * 16 + (q & 1) * 8 + g;
            if (v1a[q] - v2a[q] > C2_CERT * sqrtf(nrm2[q])) {
                rowBest[rl] = i1a[q];
            } else {
                rowBest[rl] = -1;
                int pos = atomicAdd(&g_nF, 1);
                g_flag[pos] = rowBase + rl;
            }
        }
    }
    __syncthreads();

    // ---- scatter certified rows ----
    {
        int rb = rowBest[tid];
        if (rb >= 0) atomicAdd(&g_counts[rb], 1.0f);
    }
    const float4* e4 = (const float4*)ebase;
    #pragma unroll 4
    for (int it = 0; it < 32; ++it) {
        int idx = it * 256 + tid;
        int r  = idx >> 5;
        int c4 = idx & 31;
        int rb = rowBest[r];
        if (rb >= 0) red4(&g_sums[rb * DIM + c4 * 4], e4[r * 32 + c4]);
    }
}

// ---------------------------------------------------------------------------
// RefineA: hi-fp16 GEMM on gathered 128-row flagged tiles (bulk staging) with
// top-4 tracking, then INLINE exact fp32 resolution of the top-3 candidates
// + scatter. Rows failing the top-3 cert go to g_listB.
__global__ void __launch_bounds__(256, 2)
refineA_kernel(const float* __restrict__ emb) {
    extern __shared__ char dsm[];
    const u32 sbase = smem_u32(dsm);
    int*  rowIdx = (int*)(dsm + RA_RI);
    int4* cCand  = (int4*)(dsm + RA_CC);
    const u32 mb0 = sbase + RA_MB, mb1 = mb0 + 8;

    const int tid  = threadIdx.x;
    const int wid  = tid >> 5;
    const int lane = tid & 31;
    const int g    = lane >> 2;
    const int qi   = lane & 3;

    const int nf = *(volatile int*)&g_nF;
    const int nTiles = (nf + 127) >> 7;
    const u32 laneOff = (u32)((lane & 7) * BROW_B + (lane >> 3) * 16);
    const float4* p4 = (const float4*)g_proto_n;

    if (tid == 0) { mbar_init(mb0, 1); mbar_init(mb1, 1); }
    __syncthreads();

    int pc0 = 0, pc1 = 0;   // per-stage completed-phase counters (cross-tile)

    for (int t = blockIdx.x; t < nTiles; t += gridDim.x) {
        if (tid < 128) {
            int srci = t * 128 + tid;
            rowIdx[tid] = (srci < nf) ? g_flag[srci] : -1;
        }
        __syncthreads();
        if (tid == 0) {
            mbar_expect_tx(mb0, HI_BLK); bulk_g2s(sbase, g_Bimg, HI_BLK, mb0);
            mbar_expect_tx(mb1, HI_BLK); bulk_g2s(sbase + HI_BLK, g_Bimg + HI_BLK, HI_BLK, mb1);
        }

        const int r0 = rowIdx[wid * 16 + g];
        const int r1 = rowIdx[wid * 16 + g + 8];
        const float* e0 = emb + (size_t)max(r0, 0) * DIM;
        const float* e1 = emb + (size_t)max(r1, 0) * DIM;

        u32 AHI[8][4];
        float nrm2[2] = {0.f, 0.f};
        #pragma unroll
        for (int ks = 0; ks < 8; ++ks) {
            const int c0 = ks * 16 + 2 * qi;
            float2 v0 = *(const float2*)(e0 + c0);
            float2 v1 = *(const float2*)(e1 + c0);
            float2 v2 = *(const float2*)(e0 + c0 + 8);
            float2 v3 = *(const float2*)(e1 + c0 + 8);
            AHI[ks][0] = hi2(v0); AHI[ks][1] = hi2(v1);
            AHI[ks][2] = hi2(v2); AHI[ks][3] = hi2(v3);
            nrm2[0] += v0.x * v0.x + v0.y * v0.y + v2.x * v2.x + v2.y * v2.y;
            nrm2[1] += v1.x * v1.x + v1.y * v1.y + v3.x * v3.x + v3.y * v3.y;
        }
        #pragma unroll
        for (int m = 1; m <= 2; m <<= 1) {
            nrm2[0] += __shfl_xor_sync(0xffffffffu, nrm2[0], m);
            nrm2[1] += __shfl_xor_sync(0xffffffffu, nrm2[1], m);
        }

        float V1[2], V2[2], V3[2], V4[2];
        int   I1[2], I2[2], I3[2];
        #pragma unroll
        for (int q = 0; q < 2; ++q) {
            V1[q] = V2[q] = V3[q] = V4[q] = -3.4e38f;
            I1[q] = I2[q] = I3[q] = 0;
        }

        for (int c = 0; c < NCHUNKS; ++c) {
            const int s = c & 1;
            mbar_wait(s ? mb1 : mb0, (u32)((s ? pc1 : pc0) & 1));
            const u32 bb = sbase + (u32)s * HI_BLK;

            #pragma unroll 1
            for (int nt = 0; nt < 16; ++nt) {
                float d[4] = {0.f, 0.f, 0.f, 0.f};
                u32 B[8];
                const u32 ntOff = bb + (u32)nt * (8 * BROW_B) + laneOff;
                ldsm4(B, ntOff); ldsm4(B + 4, ntOff + 64);
                #pragma unroll
                for (int ks = 0; ks < 4; ++ks) mma16(d, AHI[ks], &B[2 * ks]);
                ldsm4(B, ntOff + 128); ldsm4(B + 4, ntOff + 192);
                #pragma unroll
                for (int ks = 4; ks < 8; ++ks) mma16(d, AHI[ks], &B[2 * (ks - 4)]);

                const int c0 = c * NCHUNK_P + nt * 8 + 2 * qi;
                fold4(d[0], c0,     V1[0], I1[0], V2[0], I2[0], V3[0], I3[0], V4[0]);
                fold4(d[1], c0 + 1, V1[0], I1[0], V2[0], I2[0], V3[0], I3[0], V4[0]);
                fold4(d[2], c0,     V1[1], I1[1], V2[1], I2[1], V3[1], I3[1], V4[1]);
                fold4(d[3], c0 + 1, V1[1], I1[1], V2[1], I2[1], V3[1], I3[1], V4[1]);
            }
            if (s) ++pc1; else ++pc0;
            __syncthreads();
            if (c + 2 < NCHUNKS && tid == 0) {
                const u32 mb = s ? mb1 : mb0;
                mbar_expect_tx(mb, HI_BLK);
                bulk_g2s(sbase + (u32)s * HI_BLK, g_Bimg + (size_t)(c + 2) * HI_BLK, HI_BLK, mb);
            }
        }

        // quad merge of top-4 lists
        #pragma unroll
        for (int m = 1; m <= 2; m <<= 1) {
            #pragma unroll
            for (int q = 0; q < 2; ++q) {
                float ov1 = __shfl_xor_sync(0xffffffffu, V1[q], m);
                int   oi1 = __shfl_xor_sync(0xffffffffu, I1[q], m);
                float ov2 = __shfl_xor_sync(0xffffffffu, V2[q], m);
                int   oi2 = __shfl_xor_sync(0xffffffffu, I2[q], m);
                float ov3 = __shfl_xor_sync(0xffffffffu, V3[q], m);
                int   oi3 = __shfl_xor_sync(0xffffffffu, I3[q], m);
                float ov4 = __shfl_xor_sync(0xffffffffu, V4[q], m);
                fold4(ov1, oi1, V1[q], I1[q], V2[q], I2[q], V3[q], I3[q], V4[q]);
                fold4(ov2, oi2, V1[q], I1[q], V2[q], I2[q], V3[q], I3[q], V4[q]);
                fold4(ov3, oi3, V1[q], I1[q], V2[q], I2[q], V3[q], I3[q], V4[q]);
                V4[q] = fmaxf(V4[q], ov4);
            }
        }

        if (qi == 0) {
            #pragma unroll
            for (int q = 0; q < 2; ++q) {
                const int rl = wid * 16 + q * 8 + g;
                const int ok = (V1[q] - V4[q] > C4_CERT * sqrtf(nrm2[q])) ? 1 : 0;
                cCand[rl] = make_int4(I1[q], I2[q], I3[q], ok);
            }
        }
        __syncthreads();

        // ---- inline exact resolution: warp w handles tile rows [w*16, w*16+16) ----
        for (int rr = wid * 16; rr < wid * 16 + 16; ++rr) {
            const int row = rowIdx[rr];
            if (row < 0) continue;
            const int4 cd = cCand[rr];
            if (!cd.w) {
                if (lane == 0) { int pos = atomicAdd(&g_nB, 1); g_listB[pos] = row; }
                continue;
            }
            const float4 ef = ((const float4*)(emb + (size_t)row * DIM))[lane];
            float4 pa = p4[cd.x * 32 + lane];
            float4 pb = p4[cd.y * 32 + lane];
            float4 pc = p4[cd.z * 32 + lane];
            float d1 = fmaf(ef.x, pa.x, fmaf(ef.y, pa.y, fmaf(ef.z, pa.z, ef.w * pa.w)));
            float d2 = fmaf(ef.x, pb.x, fmaf(ef.y, pb.y, fmaf(ef.z, pb.z, ef.w * pb.w)));
            float d3 = fmaf(ef.x, pc.x, fmaf(ef.y, pc.y, fmaf(ef.z, pc.z, ef.w * pc.w)));
            #pragma unroll
            for (int m = 16; m; m >>= 1) {
                d1 += __shfl_xor_sync(0xffffffffu, d1, m);
                d2 += __shfl_xor_sync(0xffffffffu, d2, m);
                d3 += __shfl_xor_sync(0xffffffffu, d3, m);
            }
            float bv = d1; int bi = cd.x;
            if (d2 > bv || (d2 == bv && cd.y < bi)) { bv = d2; bi = cd.y; }
            if (d3 > bv || (d3 == bv && cd.z < bi)) { bv = d3; bi = cd.z; }
            if (lane == 0) atomicAdd(&g_counts[bi], 1.0f);
            red4(&g_sums[bi * DIM + lane * 4], ef);
        }
        __syncthreads();   // rowIdx/cCand reuse next tile
    }
}

// ---------------------------------------------------------------------------
// RefineB: 16-row tiles, BOTH operands staged in smem (transposed), pure
// LDS+FFMA inner loop with 16 independent chains. Warp rg owns rows 2rg,2rg+1;
// lane tx owns protos {tx*4..+3} and {128+tx*4..+3} of each 256-proto chunk.
__global__ void __launch_bounds__(256, 1)
refineB_kernel(const float* __restrict__ emb) {
    extern __shared__ char dsm[];
    float* protoS = (float*)dsm;                 // [d][pc] 128 x 256
    float* eS     = (float*)(dsm + RB_ES);       // [d][r]  128 x 16
    int*   rid    = (int*)(dsm + RB_RID);
    int*   win    = (int*)(dsm + RB_WIN);

    const int tid = threadIdx.x;
    const int tx  = tid & 31;
    const int rg  = tid >> 5;                    // warp id: rows 2rg, 2rg+1
    const int nB  = *(volatile int*)&g_nB;
    const int nTiles = (nB + 15) >> 4;

    for (int t = blockIdx.x; t < nTiles; t += gridDim.x) {
        if (tid < 16) rid[tid] = (t * 16 + tid < nB) ? g_listB[t * 16 + tid] : -1;
        __syncthreads();
        // e rows transposed into eS[d][r]
        #pragma unroll
        for (int u = 0; u < 2; ++u) {
            int idx = u * 256 + tid;
            int r = idx >> 5, c4 = idx & 31;
            int row = rid[r];
            float4 v = make_float4(0.f, 0.f, 0.f, 0.f);
            if (row >= 0) v = ((const float4*)(emb + (size_t)row * DIM))[c4];
            eS[(c4 * 4 + 0) * 16 + r] = v.x;
            eS[(c4 * 4 + 1) * 16 + r] = v.y;
            eS[(c4 * 4 + 2) * 16 + r] = v.z;
            eS[(c4 * 4 + 3) * 16 + r] = v.w;
        }

        float bv0 = -3.4e38f, bv1 = -3.4e38f;
        int   bi0 = 0, bi1 = 0;

        for (int ch = 0; ch < 4; ++ch) {
            __syncthreads();   // protoS reuse; also orders eS writes (iter 0)
            // stage 256 protos transposed: protoS[d][p]
            #pragma unroll 4
            for (int i = 0; i < 32; ++i) {
                int idx = i * 256 + tid;
                int p = idx >> 5, c4 = idx & 31;
                float4 v = ((const float4*)(g_proto_n + (size_t)(ch * 256 + p) * DIM))[c4];
                protoS[(c4 * 4 + 0) * 256 + p] = v.x;
                protoS[(c4 * 4 + 1) * 256 + p] = v.y;
                protoS[(c4 * 4 + 2) * 256 + p] = v.z;
                protoS[(c4 * 4 + 3) * 256 + p] = v.w;
            }
            __syncthreads();

            float a0[8], a1[8];
            #pragma unroll
            for (int u = 0; u < 8; ++u) { a0[u] = 0.f; a1[u] = 0.f; }
            #pragma unroll 4
            for (int d = 0; d < 128; ++d) {
                const float4 p0 = ((const float4*)(protoS + d * 256))[tx];
                const float4 p1 = ((const float4*)(protoS + d * 256 + 128))[tx];
                const float2 ev = *((const float2*)(eS + d * 16 + rg * 2));
                a0[0] = fmaf(ev.x, p0.x, a0[0]); a0[1] = fmaf(ev.x, p0.y, a0[1]);
                a0[2] = fmaf(ev.x, p0.z, a0[2]); a0[3] = fmaf(ev.x, p0.w, a0[3]);
                a0[4] = fmaf(ev.x, p1.x, a0[4]); a0[5] = fmaf(ev.x, p1.y, a0[5]);
                a0[6] = fmaf(ev.x, p1.z, a0[6]); a0[7] = fmaf(ev.x, p1.w, a0[7]);
                a1[0] = fmaf(ev.y, p0.x, a1[0]); a1[1] = fmaf(ev.y, p0.y, a1[1]);
                a1[2] = fmaf(ev.y, p0.z, a1[2]); a1[3] = fmaf(ev.y, p0.w, a1[3]);
                a1[4] = fmaf(ev.y, p1.x, a1[4]); a1[5] = fmaf(ev.y, p1.y, a1[5]);
                a1[6] = fmaf(ev.y, p1.z, a1[6]); a1[7] = fmaf(ev.y, p1.w, a1[7]);
            }
            // fold ascending (strict > = first-max per thread)
            #pragma unroll
            for (int u = 0; u < 4; ++u) {
                int c = ch * 256 + tx * 4 + u;
                if (a0[u] > bv0) { bv0 = a0[u]; bi0 = c; }
                if (a1[u] > bv1) { bv1 = a1[u]; bi1 = c; }
            }
            #pragma unroll
            for (int u = 0; u < 4; ++u) {
                int c = ch * 256 + 128 + tx * 4 + u;
                if (a0[4 + u] > bv0) { bv0 = a0[4 + u]; bi0 = c; }
                if (a1[4 + u] > bv1) { bv1 = a1[4 + u]; bi1 = c; }
            }
        }

        // warp merge (value desc, index asc tie-break)
        #pragma unroll
        for (int m = 16; m; m >>= 1) {
            float ov = __shfl_xor_sync(0xffffffffu, bv0, m);
            int   oi = __shfl_xor_sync(0xffffffffu, bi0, m);
            if (ov > bv0 || (ov == bv0 && oi < bi0)) { bv0 = ov; bi0 = oi; }
            ov = __shfl_xor_sync(0xffffffffu, bv1, m);
            oi = __shfl_xor_sync(0xffffffffu, bi1, m);
            if (ov > bv1 || (ov == bv1 && oi < bi1)) { bv1 = ov; bi1 = oi; }
        }
        if (tx == 0) {
            win[rg * 2]     = bi0;
            win[rg * 2 + 1] = bi1;
            if (rid[rg * 2] >= 0)     atomicAdd(&g_counts[bi0], 1.0f);
            if (rid[rg * 2 + 1] >= 0) atomicAdd(&g_counts[bi1], 1.0f);
        }
        __syncthreads();

        // scatter rows (emb re-read hits L2/L1)
        #pragma unroll
        for (int u = 0; u < 2; ++u) {
            int idx = u * 256 + tid;
            int r = idx >> 5, c4 = idx & 31;
            int row = rid[r];
            if (row >= 0) {
                float4 v = ((const float4*)(emb + (size_t)row * DIM))[c4];
                red4(&g_sums[win[r] * DIM + c4 * 4], v);
            }
        }
        __syncthreads();   // rid/win reuse next tile
    }
}

// ---------------------------------------------------------------------------
__global__ void finalize_kernel(const float* __restrict__ proto,
                                float* __restrict__ out) {
    int i = blockIdx.x * blockDim.x + threadIdx.x;
    int k = i >> 7;
    float c = g_counts[k];
    float p = proto[i];
    float m = g_sums[i] / fmaxf(c, 1.0f);
    out[i] = (c > 0.0f) ? (0.9f * p + 0.1f * m) : p;
}

// ---------------------------------------------------------------------------
extern "C" void kernel_launch(void* const* d_in, const int* in_sizes, int n_in,
                              void* d_out, int out_size) {
    const float* emb   = (const float*)d_in[0];
    const float* proto = (const float*)d_in[1];
    float* out = (float*)d_out;

    cudaFuncSetAttribute(pass1_kernel,
                         cudaFuncAttributeMaxDynamicSharedMemorySize, P1_SMEM);
    cudaFuncSetAttribute(refineA_kernel,
                         cudaFuncAttributeMaxDynamicSharedMemorySize, RA_SMEM);
    cudaFuncSetAttribute(refineB_kernel,
                         cudaFuncAttributeMaxDynamicSharedMemorySize, RB_SMEM);

    prep_kernel<<<KCL, DIM>>>(proto);
    pass1_kernel<<<BROWS / M_CTA, 256, P1_SMEM>>>(emb);
    refineA_kernel<<<148, 256, RA_SMEM>>>(emb);
    refineB_kernel<<<128, 256, RB_SMEM>>>(emb);
    finalize_kernel<<<(KCL * DIM) / 256, 256>>>(proto, out);
}